// round 15
// baseline (speedup 1.0000x reference)
#include <cuda_runtime.h>
#include <cuda_fp16.h>
#include <cstdint>

// ---------------- problem constants ----------------
#define NBATCH   32
#define C_DIM    256
#define PIX      4096
#define KCL      128
#define OUT_BINS 129
#define TILE_P   128
#define NTH      512                    // 16 warps, warp tile 32px x 32cl
#define KC       32
#define NCHUNK   8
#define DELTA    0.4f                   // >= 2*max|dist err| of fp16 hi-only pass
#define LIST_CAP 2048

// smem word (4B) layout
#define RAW_PITCH 128                   // fp32 x chunk [ch][px]
#define RAW_WORDS (KC * RAW_PITCH)      // 4096, x3 stages
#define P16       20                    // half2 pitch (ldmatrix conflict-free)
#define A16_WORDS (TILE_P * P16)        // 2560, x2 stages
#define B16_WORDS (KCL * P16)           // 2560, x3 stages
#define OFF_RAW   0
#define OFF_A16   (3 * RAW_WORDS)       // 12288
#define OFF_B16   (OFF_A16 + 2 * A16_WORDS)  // 17408
#define SMEM_WORDS (OFF_B16 + 3 * B16_WORDS) // 25088 -> 100352 B

__device__ float   g_c2[KCL];
__device__ __half2 g_cent_hi[KCL * 128];    // [cl][ch2]

// ---------------- helpers ----------------
__device__ __forceinline__ uint32_t smem_u32(const void* p) {
    uint32_t a;
    asm("{ .reg .u64 t; cvta.to.shared.u64 t, %1; cvt.u32.u64 %0, t; }" : "=r"(a) : "l"(p));
    return a;
}
__device__ __forceinline__ void cpasync16(uint32_t dst, const void* src) {
    asm volatile("cp.async.cg.shared.global [%0], [%1], 16;" :: "r"(dst), "l"(src));
}
__device__ __forceinline__ void ldsm_x4(uint32_t& r0, uint32_t& r1, uint32_t& r2, uint32_t& r3,
                                        uint32_t addr) {
    asm volatile("ldmatrix.sync.aligned.m8n8.x4.shared.b16 {%0,%1,%2,%3}, [%4];"
                 : "=r"(r0), "=r"(r1), "=r"(r2), "=r"(r3) : "r"(addr));
}
__device__ __forceinline__ void mma_f16(float& d0, float& d1, float& d2, float& d3,
                                        uint32_t a0, uint32_t a1, uint32_t a2, uint32_t a3,
                                        uint32_t b0, uint32_t b1) {
    asm volatile(
        "mma.sync.aligned.m16n8k16.row.col.f32.f16.f16.f32 "
        "{%0,%1,%2,%3}, {%4,%5,%6,%7}, {%8,%9}, {%0,%1,%2,%3};"
        : "+f"(d0), "+f"(d1), "+f"(d2), "+f"(d3)
        : "r"(a0), "r"(a1), "r"(a2), "r"(a3), "r"(b0), "r"(b1));
}
__device__ __forceinline__ uint32_t fkey(float f) {
    uint32_t u = __float_as_uint(f);
    return u ^ ((u & 0x80000000u) ? 0xFFFFFFFFu : 0x80000000u);
}
__device__ __forceinline__ float unfkey(uint32_t k) {
    uint32_t u = (k & 0x80000000u) ? (k ^ 0x80000000u) : ~k;
    return __uint_as_float(u);
}

// ---------------- prep: centers -> fp16 hi + exact c2 ----------------
__global__ void prep_kernel(const float* __restrict__ centers) {
    int warp = (blockIdx.x * blockDim.x + threadIdx.x) >> 5;   // cluster
    int lane = threadIdx.x & 31;
    if (warp >= KCL) return;
    const float* row = centers + (size_t)warp * C_DIM;
    float s = 0.f;
#pragma unroll
    for (int j = 0; j < 4; ++j) {
        int ch2 = lane + 32 * j;
        float f0 = row[2 * ch2];
        float f1 = row[2 * ch2 + 1];
        s = fmaf(f0, f0, fmaf(f1, f1, s));
        g_cent_hi[warp * 128 + ch2] = __floats2half2_rn(f0, f1);
    }
#pragma unroll
    for (int o = 16; o >= 1; o >>= 1) s += __shfl_xor_sync(0xffffffffu, s, o);
    if (lane == 0) g_c2[warp] = s;
}

// ---------------- main kernel ----------------
__global__ __launch_bounds__(NTH, 2)
void vq_mma_kernel(const float* __restrict__ x,
                   const float* __restrict__ centers,
                   float* __restrict__ out) {
    extern __shared__ float smem[];
    const uint32_t smem_b = smem_u32(smem);

    const int tid  = threadIdx.x;
    const int wid  = tid >> 5;              // 0..15
    const int lane = tid & 31;
    const int g    = lane >> 2;
    const int t    = lane & 3;

    const int pm = (wid & 3) * 32;          // pixel quarter
    const int cn = (wid >> 2) * 32;         // cluster quarter

    const int ct = blockIdx.x;
    const int n  = ct >> 5;
    const int p0 = (ct & 31) * TILE_P;
    const float* xn = x + (size_t)n * C_DIM * PIX + p0;

    float acc[2][4][4];
#pragma unroll
    for (int mt = 0; mt < 2; ++mt)
#pragma unroll
        for (int nt = 0; nt < 4; ++nt)
#pragma unroll
            for (int c = 0; c < 4; ++c) acc[mt][nt][c] = 0.f;

    auto issue_x = [&](int chunk, int s) {
        const int ch0 = chunk * KC;
        const uint32_t base = smem_b + (uint32_t)(OFF_RAW + s * RAW_WORDS) * 4u;
#pragma unroll
        for (int i = 0; i < 2; ++i) {       // 1024 x 16B
            int idx = tid + NTH * i;
            int ch  = idx >> 5;
            int sg  = idx & 31;
            cpasync16(base + (uint32_t)(ch * RAW_PITCH + sg * 4) * 4u,
                      xn + (size_t)(ch0 + ch) * PIX + sg * 4);
        }
        asm volatile("cp.async.commit_group;" ::: "memory");
    };
    auto issue_b = [&](int chunk, int s) {
        const uint32_t base = smem_b + (uint32_t)(OFF_B16 + s * B16_WORDS) * 4u;
        int cl  = tid >> 2;
        int seg = tid & 3;
        cpasync16(base + (uint32_t)(cl * P16 + seg * 4) * 4u,
                  g_cent_hi + (size_t)cl * 128 + chunk * 16 + seg * 4);
        asm volatile("cp.async.commit_group;" ::: "memory");
    };

    // prologue: chunks 0,1 in flight (groups: X0,B0,X1,B1)
    issue_x(0, 0); issue_b(0, 0);
    issue_x(1, 1); issue_b(1, 1);

    // ldmatrix per-thread base addresses (stage 0)
    const uint32_t a_ldsm0 = smem_b + (uint32_t)(OFF_A16
        + (pm + ((lane >> 3) & 1) * 8 + (lane & 7)) * P16 + (lane >> 4) * 4) * 4u;
    const uint32_t b_ldsm0 = smem_b + (uint32_t)(OFF_B16
        + (cn + (lane >> 4) * 8 + (lane & 7)) * P16 + ((lane >> 3) & 1) * 4) * 4u;
    // convert: thread writes px = tid&127, ch2 = 4q..4q+3 (q = tid>>7)
    const int cv_px = tid & 127;
    const int cv_q  = tid >> 7;
    const uint32_t cv_sts0 = smem_b + (uint32_t)(OFF_A16 + cv_px * P16 + cv_q * 4) * 4u;

    for (int c = 0; c < NCHUNK; ++c) {
        if (c < NCHUNK - 1) asm volatile("cp.async.wait_group 2;" ::: "memory");
        else                asm volatile("cp.async.wait_group 0;" ::: "memory");
        __syncthreads();                                   // S1: raw(c%3), B(c%3) ready

        // early issue for chunk c+2 (stages (c+2)%3 — no alias with c or c+1)
        if (c + 2 < NCHUNK) {
            issue_x(c + 2, (c + 2) % 3);
            issue_b(c + 2, (c + 2) % 3);
        }

        // ---- convert raw(c%3) -> A16(c&1): 8 LDS + 1 st.v4 per thread ----
        {
            const float* raw = smem + OFF_RAW + (size_t)(c % 3) * RAW_WORDS;
            __half2 h[4];
#pragma unroll
            for (int j = 0; j < 4; ++j) {
                float f0 = raw[(8 * cv_q + 2 * j)     * RAW_PITCH + cv_px];
                float f1 = raw[(8 * cv_q + 2 * j + 1) * RAW_PITCH + cv_px];
                h[j] = __floats2half2_rn(f0, f1);
            }
            uint32_t addr = cv_sts0 + (uint32_t)((c & 1) * A16_WORDS) * 4u;
            asm volatile("st.shared.v4.b32 [%0], {%1,%2,%3,%4};"
                         :: "r"(addr),
                            "r"(*reinterpret_cast<uint32_t*>(&h[0])),
                            "r"(*reinterpret_cast<uint32_t*>(&h[1])),
                            "r"(*reinterpret_cast<uint32_t*>(&h[2])),
                            "r"(*reinterpret_cast<uint32_t*>(&h[3])));
        }
        __syncthreads();                                   // S2: A16(c&1) visible

        // ---- MMA: 2 k16-slices via ldmatrix ----
        {
            const uint32_t aS = a_ldsm0 + (uint32_t)((c & 1) * A16_WORDS) * 4u;
            const uint32_t bS = b_ldsm0 + (uint32_t)((c % 3) * B16_WORDS) * 4u;
#pragma unroll
            for (int sl = 0; sl < 2; ++sl) {
                const uint32_t ko = (uint32_t)(sl * 8) * 4u;   // +8 half2 per slice
                uint32_t a[2][4], b[4][2];
                ldsm_x4(a[0][0], a[0][1], a[0][2], a[0][3], aS + ko);                     // mt0
                ldsm_x4(a[1][0], a[1][1], a[1][2], a[1][3], aS + ko + 16u * P16 * 4u);    // mt1
                ldsm_x4(b[0][0], b[0][1], b[1][0], b[1][1], bS + ko);                     // nt0,1
                ldsm_x4(b[2][0], b[2][1], b[3][0], b[3][1], bS + ko + 16u * P16 * 4u);    // nt2,3
#pragma unroll
                for (int nt = 0; nt < 4; ++nt)
#pragma unroll
                    for (int mt = 0; mt < 2; ++mt)
                        mma_f16(acc[mt][nt][0], acc[mt][nt][1], acc[mt][nt][2], acc[mt][nt][3],
                                a[mt][0], a[mt][1], a[mt][2], a[mt][3],
                                b[nt][0], b[nt][1]);
            }
        }
        // no S3: next iteration's S1 fences these reads before any aliasing write
    }

    // ---------------- epilogue (proven rescue machinery) ----------------
    unsigned long long* apxkey   = reinterpret_cast<unsigned long long*>(smem);       // [128]
    unsigned long long* exactkey = apxkey + 128;                                      // [128]
    unsigned int*       cnt      = reinterpret_cast<unsigned int*>(exactkey + 128);   // [128]
    unsigned int*       list     = cnt + 128;                                         // [LIST_CAP]
    unsigned int*       listn    = list + LIST_CAP;

    __syncthreads();
    if (tid < TILE_P) {
        apxkey[tid]   = ~0ull;
        exactkey[tid] = ~0ull;
        cnt[tid]      = 0u;
    }
    if (tid == 0) *listn = 0u;
    __syncthreads();

    float c2v[4][2];
#pragma unroll
    for (int nt = 0; nt < 4; ++nt) {
        c2v[nt][0] = g_c2[cn + nt * 8 + t * 2];
        c2v[nt][1] = g_c2[cn + nt * 8 + t * 2 + 1];
    }

    // phase A: approx argmin per pixel
#pragma unroll
    for (int mt = 0; mt < 2; ++mt)
#pragma unroll
        for (int rh = 0; rh < 2; ++rh) {
            const int px = pm + mt * 16 + rh * 8 + g;
            float bv = 3.4e38f; int bk = -1;
#pragma unroll
            for (int nt = 0; nt < 4; ++nt)
#pragma unroll
                for (int cc = 0; cc < 2; ++cc) {
                    float d = fmaf(-2.f, acc[mt][nt][rh * 2 + cc], c2v[nt][cc]);
                    if (d < bv) { bv = d; bk = cn + nt * 8 + t * 2 + cc; }
                }
            unsigned long long key = ((unsigned long long)fkey(bv) << 32) | (unsigned)bk;
            unsigned long long o = __shfl_xor_sync(0xffffffffu, key, 1);
            if (o < key) key = o;
            o = __shfl_xor_sync(0xffffffffu, key, 2);
            if (o < key) key = o;
            if (t == 0) atomicMin(&apxkey[px], key);
        }
    __syncthreads();

    // phase B1: count candidates within DELTA of approx min
#pragma unroll
    for (int mt = 0; mt < 2; ++mt)
#pragma unroll
        for (int rh = 0; rh < 2; ++rh) {
            const int px = pm + mt * 16 + rh * 8 + g;
            const float thr = unfkey((uint32_t)(apxkey[px] >> 32)) + DELTA;
            int cl = 0;
#pragma unroll
            for (int nt = 0; nt < 4; ++nt)
#pragma unroll
                for (int cc = 0; cc < 2; ++cc)
                    if (fmaf(-2.f, acc[mt][nt][rh * 2 + cc], c2v[nt][cc]) <= thr) ++cl;
            if (cl) atomicAdd(&cnt[px], (unsigned)cl);
        }
    __syncthreads();

    // phase B2: push only ambiguous pixels' candidates
#pragma unroll
    for (int mt = 0; mt < 2; ++mt)
#pragma unroll
        for (int rh = 0; rh < 2; ++rh) {
            const int px = pm + mt * 16 + rh * 8 + g;
            if (cnt[px] < 2u) continue;
            const float thr = unfkey((uint32_t)(apxkey[px] >> 32)) + DELTA;
#pragma unroll
            for (int nt = 0; nt < 4; ++nt)
#pragma unroll
                for (int cc = 0; cc < 2; ++cc)
                    if (fmaf(-2.f, acc[mt][nt][rh * 2 + cc], c2v[nt][cc]) <= thr) {
                        unsigned e = ((unsigned)px << 8) |
                                     (unsigned)(cn + nt * 8 + t * 2 + cc);
                        unsigned il = atomicAdd(listn, 1u);
                        if (il < LIST_CAP) list[il] = e;
                    }
        }
    __syncthreads();

    // phase C: warp-cooperative exact fp32 rescue
    const int nl = (int)min(*listn, (unsigned)LIST_CAP);
    for (int i = wid; i < nl; i += 16) {
        unsigned e = list[i];
        int px = e >> 8, k = e & 255;
        const float* cr = centers + (size_t)k * C_DIM;
        float s = 0.f;
#pragma unroll
        for (int j = 0; j < 8; ++j) {
            int cc = lane * 8 + j;
            s = fmaf(__ldg(xn + (size_t)cc * PIX + px), __ldg(cr + cc), s);
        }
#pragma unroll
        for (int o = 16; o >= 1; o >>= 1) s += __shfl_xor_sync(0xffffffffu, s, o);
        if (lane == 0) {
            float ed = fmaf(-2.f, s, g_c2[k]);
            atomicMin(&exactkey[px],
                      ((unsigned long long)fkey(ed) << 32) | (unsigned)k);
        }
    }
    __syncthreads();

    // histogram
    if (tid < TILE_P) {
        unsigned long long key = (cnt[tid] >= 2u) ? exactkey[tid] : apxkey[tid];
        int bi = (int)(unsigned)(key & 0xFFFFFFFFull);
        int pg = p0 + tid;
        int h = pg >> 6, w = pg & 63;
        int sblk = (h >> 3) * 8 + (w >> 3);
        atomicAdd(&out[((size_t)n * 64 + sblk) * OUT_BINS + bi + 1], 1.0f / 64.0f);
    }
}

// ---------------- launch ----------------
#define SMEM_BYTES (SMEM_WORDS * 4)     // 100352

extern "C" void kernel_launch(void* const* d_in, const int* in_sizes, int n_in,
                              void* d_out, int out_size) {
    const float* x       = (const float*)d_in[0];
    const float* centers = (const float*)d_in[1];
    float* out           = (float*)d_out;

    cudaFuncSetAttribute(vq_mma_kernel, cudaFuncAttributeMaxDynamicSharedMemorySize, SMEM_BYTES);

    cudaMemsetAsync(d_out, 0, (size_t)out_size * sizeof(float), 0);
    prep_kernel<<<(KCL * 32 + 255) / 256, 256>>>(centers);

    int nblocks = (NBATCH * PIX) / TILE_P;   // 1024
    vq_mma_kernel<<<nblocks, NTH, SMEM_BYTES>>>(x, centers, out);
}

// round 16
// speedup vs baseline: 1.1000x; 1.1000x over previous
#include <cuda_runtime.h>
#include <cuda_fp16.h>
#include <cstdint>

// ---------------- problem constants ----------------
#define NBATCH   32
#define C_DIM    256
#define PIX      4096
#define KCL      128
#define OUT_BINS 129
#define TILE_P   128
#define NTH      512                    // 16 warps, warp tile 32px x 32cl
#define KC       32
#define NCHUNK   8
#define DELTA    0.4f                   // >= 2*max|dist err| of fp16 hi-only pass
#define LIST_CAP 2048

// smem word (4B) layout  (R13-proven: 73.7 KB, 2 CTAs/SM, L1D ~81 KB)
#define RAW_PITCH 128                   // fp32 x chunk [ch][px]
#define RAW_WORDS (KC * RAW_PITCH)      // 4096, x2 stages
#define P16       20                    // half2 pitch (ldmatrix conflict-free)
#define A16_WORDS (TILE_P * P16)        // 2560, x2 stages
#define B16_WORDS (KCL * P16)           // 2560, x2 stages
#define OFF_RAW   0
#define OFF_A16   (2 * RAW_WORDS)       // 8192
#define OFF_B16   (OFF_A16 + 2 * A16_WORDS)  // 13312
#define SMEM_WORDS (OFF_B16 + 2 * B16_WORDS) // 18432 -> 73728 B

__device__ float   g_c2[KCL];
__device__ __half2 g_cent_hi[KCL * 128];    // [cl][ch2]

// ---------------- helpers ----------------
__device__ __forceinline__ uint32_t smem_u32(const void* p) {
    uint32_t a;
    asm("{ .reg .u64 t; cvta.to.shared.u64 t, %1; cvt.u32.u64 %0, t; }" : "=r"(a) : "l"(p));
    return a;
}
__device__ __forceinline__ void cpasync16(uint32_t dst, const void* src) {
    asm volatile("cp.async.cg.shared.global [%0], [%1], 16;" :: "r"(dst), "l"(src));
}
__device__ __forceinline__ void ldsm_x4(uint32_t& r0, uint32_t& r1, uint32_t& r2, uint32_t& r3,
                                        uint32_t addr) {
    asm volatile("ldmatrix.sync.aligned.m8n8.x4.shared.b16 {%0,%1,%2,%3}, [%4];"
                 : "=r"(r0), "=r"(r1), "=r"(r2), "=r"(r3) : "r"(addr));
}
__device__ __forceinline__ void mma_f16(float& d0, float& d1, float& d2, float& d3,
                                        uint32_t a0, uint32_t a1, uint32_t a2, uint32_t a3,
                                        uint32_t b0, uint32_t b1) {
    asm volatile(
        "mma.sync.aligned.m16n8k16.row.col.f32.f16.f16.f32 "
        "{%0,%1,%2,%3}, {%4,%5,%6,%7}, {%8,%9}, {%0,%1,%2,%3};"
        : "+f"(d0), "+f"(d1), "+f"(d2), "+f"(d3)
        : "r"(a0), "r"(a1), "r"(a2), "r"(a3), "r"(b0), "r"(b1));
}
__device__ __forceinline__ uint32_t fkey(float f) {
    uint32_t u = __float_as_uint(f);
    return u ^ ((u & 0x80000000u) ? 0xFFFFFFFFu : 0x80000000u);
}
__device__ __forceinline__ float unfkey(uint32_t k) {
    uint32_t u = (k & 0x80000000u) ? (k ^ 0x80000000u) : ~k;
    return __uint_as_float(u);
}

// ---------------- prep: centers -> fp16 hi + exact c2 + zero out ----------------
__global__ void prep_kernel(const float* __restrict__ centers,
                            float* __restrict__ out, int out_size) {
    int gtid = blockIdx.x * blockDim.x + threadIdx.x;
    // zero the output histogram (replaces cudaMemsetAsync)
    for (int i = gtid; i < out_size; i += 4096) out[i] = 0.f;

    int warp = gtid >> 5;                  // cluster
    int lane = threadIdx.x & 31;
    if (warp >= KCL) return;
    const float* row = centers + (size_t)warp * C_DIM;
    float s = 0.f;
#pragma unroll
    for (int j = 0; j < 4; ++j) {
        int ch2 = lane + 32 * j;
        float f0 = row[2 * ch2];
        float f1 = row[2 * ch2 + 1];
        s = fmaf(f0, f0, fmaf(f1, f1, s));
        g_cent_hi[warp * 128 + ch2] = __floats2half2_rn(f0, f1);
    }
#pragma unroll
    for (int o = 16; o >= 1; o >>= 1) s += __shfl_xor_sync(0xffffffffu, s, o);
    if (lane == 0) g_c2[warp] = s;
}

// ---------------- main kernel ----------------
__global__ __launch_bounds__(NTH, 2)
void vq_mma_kernel(const float* __restrict__ x,
                   const float* __restrict__ centers,
                   float* __restrict__ out) {
    extern __shared__ float smem[];
    const uint32_t smem_b = smem_u32(smem);

    const int tid  = threadIdx.x;
    const int wid  = tid >> 5;              // 0..15
    const int lane = tid & 31;
    const int g    = lane >> 2;
    const int t    = lane & 3;

    const int pm = (wid & 3) * 32;          // pixel quarter
    const int cn = (wid >> 2) * 32;         // cluster quarter

    const int ct = blockIdx.x;
    const int n  = ct >> 5;
    const int p0 = (ct & 31) * TILE_P;
    const float* xn = x + (size_t)n * C_DIM * PIX + p0;

    float acc[2][4][4];
#pragma unroll
    for (int mt = 0; mt < 2; ++mt)
#pragma unroll
        for (int nt = 0; nt < 4; ++nt)
#pragma unroll
            for (int c = 0; c < 4; ++c) acc[mt][nt][c] = 0.f;

    auto issue_x = [&](int chunk, int s) {
        const int ch0 = chunk * KC;
        const uint32_t base = smem_b + (uint32_t)(OFF_RAW + s * RAW_WORDS) * 4u;
#pragma unroll
        for (int i = 0; i < 2; ++i) {       // 1024 x 16B
            int idx = tid + NTH * i;
            int ch  = idx >> 5;
            int sg  = idx & 31;
            cpasync16(base + (uint32_t)(ch * RAW_PITCH + sg * 4) * 4u,
                      xn + (size_t)(ch0 + ch) * PIX + sg * 4);
        }
        asm volatile("cp.async.commit_group;" ::: "memory");
    };
    auto issue_b = [&](int chunk, int s) {
        const uint32_t base = smem_b + (uint32_t)(OFF_B16 + s * B16_WORDS) * 4u;
        int cl  = tid >> 2;
        int seg = tid & 3;
        cpasync16(base + (uint32_t)(cl * P16 + seg * 4) * 4u,
                  g_cent_hi + (size_t)cl * 128 + chunk * 16 + seg * 4);
        asm volatile("cp.async.commit_group;" ::: "memory");
    };

    // prologue: chunks 0,1 in flight (groups: X0,B0,X1,B1)
    issue_x(0, 0); issue_b(0, 0);
    issue_x(1, 1); issue_b(1, 1);

    // ldmatrix per-thread base addresses (stage 0)
    const uint32_t a_ldsm0 = smem_b + (uint32_t)(OFF_A16
        + (pm + ((lane >> 3) & 1) * 8 + (lane & 7)) * P16 + (lane >> 4) * 4) * 4u;
    const uint32_t b_ldsm0 = smem_b + (uint32_t)(OFF_B16
        + (cn + (lane >> 4) * 8 + (lane & 7)) * P16 + ((lane >> 3) & 1) * 4) * 4u;
    // convert: thread writes px = tid&127, ch2 = 4q..4q+3 (q = tid>>7)
    const int cv_px = tid & 127;
    const int cv_q  = tid >> 7;
    const uint32_t cv_sts0 = smem_b + (uint32_t)(OFF_A16 + cv_px * P16 + cv_q * 4) * 4u;

    for (int c = 0; c < NCHUNK; ++c) {
        if (c < NCHUNK - 1) asm volatile("cp.async.wait_group 2;" ::: "memory");
        else                asm volatile("cp.async.wait_group 0;" ::: "memory");
        __syncthreads();                                   // S1: raw(c&1), B(c&1) ready

        // ---- convert raw(c&1) -> A16(c&1): 8 LDS + 1 st.v4 per thread ----
        {
            const float* raw = smem + OFF_RAW + (size_t)(c & 1) * RAW_WORDS;
            __half2 h[4];
#pragma unroll
            for (int j = 0; j < 4; ++j) {
                float f0 = raw[(8 * cv_q + 2 * j)     * RAW_PITCH + cv_px];
                float f1 = raw[(8 * cv_q + 2 * j + 1) * RAW_PITCH + cv_px];
                h[j] = __floats2half2_rn(f0, f1);
            }
            uint32_t addr = cv_sts0 + (uint32_t)((c & 1) * A16_WORDS) * 4u;
            asm volatile("st.shared.v4.b32 [%0], {%1,%2,%3,%4};"
                         :: "r"(addr),
                            "r"(*reinterpret_cast<uint32_t*>(&h[0])),
                            "r"(*reinterpret_cast<uint32_t*>(&h[1])),
                            "r"(*reinterpret_cast<uint32_t*>(&h[2])),
                            "r"(*reinterpret_cast<uint32_t*>(&h[3])));
        }
        __syncthreads();                                   // S2: A16(c&1) visible
        if (c + 2 < NCHUNK) issue_x(c + 2, c & 1);         // raw(c&1) free

        // ---- MMA: 2 k16-slices via ldmatrix ----
        {
            const uint32_t aS = a_ldsm0 + (uint32_t)((c & 1) * A16_WORDS) * 4u;
            const uint32_t bS = b_ldsm0 + (uint32_t)((c & 1) * B16_WORDS) * 4u;
#pragma unroll
            for (int sl = 0; sl < 2; ++sl) {
                const uint32_t ko = (uint32_t)(sl * 8) * 4u;   // +8 half2 per slice
                uint32_t a[2][4], b[4][2];
                ldsm_x4(a[0][0], a[0][1], a[0][2], a[0][3], aS + ko);                     // mt0
                ldsm_x4(a[1][0], a[1][1], a[1][2], a[1][3], aS + ko + 16u * P16 * 4u);    // mt1
                ldsm_x4(b[0][0], b[0][1], b[1][0], b[1][1], bS + ko);                     // nt0,1
                ldsm_x4(b[2][0], b[2][1], b[3][0], b[3][1], bS + ko + 16u * P16 * 4u);    // nt2,3
#pragma unroll
                for (int nt = 0; nt < 4; ++nt)
#pragma unroll
                    for (int mt = 0; mt < 2; ++mt)
                        mma_f16(acc[mt][nt][0], acc[mt][nt][1], acc[mt][nt][2], acc[mt][nt][3],
                                a[mt][0], a[mt][1], a[mt][2], a[mt][3],
                                b[nt][0], b[nt][1]);
            }
        }
        __syncthreads();                                   // S3: A16/B16(c&1) reads done
        if (c + 2 < NCHUNK) issue_b(c + 2, c & 1);
    }

    // ---------------- epilogue ----------------
    // Overlay occupies words 0..~2.7K (raw stage-0 region). No barrier needed
    // before init: concurrent warps finishing iteration 7 only touch words
    // >= OFF_A16 (8192) and raw stage 1 (4096..8191) — disjoint.
    unsigned long long* apxkey   = reinterpret_cast<unsigned long long*>(smem);       // [128]
    unsigned long long* exactkey = apxkey + 128;                                      // [128]
    unsigned int*       cnt      = reinterpret_cast<unsigned int*>(exactkey + 128);   // [128]
    unsigned int*       list     = cnt + 128;                                         // [LIST_CAP]
    unsigned int*       listn    = list + LIST_CAP;

    if (tid < TILE_P) {
        apxkey[tid]   = ~0ull;
        exactkey[tid] = ~0ull;
        cnt[tid]      = 0u;
    }
    if (tid == 0) *listn = 0u;
    __syncthreads();

    float c2v[4][2];
#pragma unroll
    for (int nt = 0; nt < 4; ++nt) {
        c2v[nt][0] = g_c2[cn + nt * 8 + t * 2];
        c2v[nt][1] = g_c2[cn + nt * 8 + t * 2 + 1];
    }

    // phase A: approx argmin per pixel
#pragma unroll
    for (int mt = 0; mt < 2; ++mt)
#pragma unroll
        for (int rh = 0; rh < 2; ++rh) {
            const int px = pm + mt * 16 + rh * 8 + g;
            float bv = 3.4e38f; int bk = -1;
#pragma unroll
            for (int nt = 0; nt < 4; ++nt)
#pragma unroll
                for (int cc = 0; cc < 2; ++cc) {
                    float d = fmaf(-2.f, acc[mt][nt][rh * 2 + cc], c2v[nt][cc]);
                    if (d < bv) { bv = d; bk = cn + nt * 8 + t * 2 + cc; }
                }
            unsigned long long key = ((unsigned long long)fkey(bv) << 32) | (unsigned)bk;
            unsigned long long o = __shfl_xor_sync(0xffffffffu, key, 1);
            if (o < key) key = o;
            o = __shfl_xor_sync(0xffffffffu, key, 2);
            if (o < key) key = o;
            if (t == 0) atomicMin(&apxkey[px], key);
        }
    __syncthreads();

    // phase B1: count candidates within DELTA; record per-thread masks
    uint32_t cmask[2][2];
#pragma unroll
    for (int mt = 0; mt < 2; ++mt)
#pragma unroll
        for (int rh = 0; rh < 2; ++rh) {
            const int px = pm + mt * 16 + rh * 8 + g;
            const float thr = unfkey((uint32_t)(apxkey[px] >> 32)) + DELTA;
            uint32_t m = 0;
            int cl = 0;
#pragma unroll
            for (int nt = 0; nt < 4; ++nt)
#pragma unroll
                for (int cc = 0; cc < 2; ++cc)
                    if (fmaf(-2.f, acc[mt][nt][rh * 2 + cc], c2v[nt][cc]) <= thr) {
                        m |= 1u << (nt * 2 + cc);
                        ++cl;
                    }
            cmask[mt][rh] = m;
            if (cl) atomicAdd(&cnt[px], (unsigned)cl);
        }
    __syncthreads();

    // phase B2: push only ambiguous pixels' candidates (reuse masks)
#pragma unroll
    for (int mt = 0; mt < 2; ++mt)
#pragma unroll
        for (int rh = 0; rh < 2; ++rh) {
            const int px = pm + mt * 16 + rh * 8 + g;
            uint32_t m = cmask[mt][rh];
            if (m == 0u || cnt[px] < 2u) continue;
            while (m) {
                int b = __ffs(m) - 1;
                m &= m - 1;
                int nt = b >> 1, cc = b & 1;
                unsigned e = ((unsigned)px << 8) |
                             (unsigned)(cn + nt * 8 + t * 2 + cc);
                unsigned il = atomicAdd(listn, 1u);
                if (il < LIST_CAP) list[il] = e;
            }
        }
    __syncthreads();

    // phase C: warp-cooperative exact fp32 rescue
    const int nl = (int)min(*listn, (unsigned)LIST_CAP);
    for (int i = wid; i < nl; i += 16) {
        unsigned e = list[i];
        int px = e >> 8, k = e & 255;
        const float* cr = centers + (size_t)k * C_DIM;
        float s = 0.f;
#pragma unroll
        for (int j = 0; j < 8; ++j) {
            int cc = lane * 8 + j;
            s = fmaf(__ldg(xn + (size_t)cc * PIX + px), __ldg(cr + cc), s);
        }
#pragma unroll
        for (int o = 16; o >= 1; o >>= 1) s += __shfl_xor_sync(0xffffffffu, s, o);
        if (lane == 0) {
            float ed = fmaf(-2.f, s, g_c2[k]);
            atomicMin(&exactkey[px],
                      ((unsigned long long)fkey(ed) << 32) | (unsigned)k);
        }
    }
    __syncthreads();

    // histogram
    if (tid < TILE_P) {
        unsigned long long key = (cnt[tid] >= 2u) ? exactkey[tid] : apxkey[tid];
        int bi = (int)(unsigned)(key & 0xFFFFFFFFull);
        int pg = p0 + tid;
        int h = pg >> 6, w = pg & 63;
        int sblk = (h >> 3) * 8 + (w >> 3);
        atomicAdd(&out[((size_t)n * 64 + sblk) * OUT_BINS + bi + 1], 1.0f / 64.0f);
    }
}

// ---------------- launch ----------------
#define SMEM_BYTES (SMEM_WORDS * 4)     // 73728

extern "C" void kernel_launch(void* const* d_in, const int* in_sizes, int n_in,
                              void* d_out, int out_size) {
    const float* x       = (const float*)d_in[0];
    const float* centers = (const float*)d_in[1];
    float* out           = (float*)d_out;

    cudaFuncSetAttribute(vq_mma_kernel, cudaFuncAttributeMaxDynamicSharedMemorySize, SMEM_BYTES);

    prep_kernel<<<16, 256>>>(centers, out, out_size);   // zeroes out + builds c2/cent16

    int nblocks = (NBATCH * PIX) / TILE_P;   // 1024
    vq_mma_kernel<<<nblocks, NTH, SMEM_BYTES>>>(x, centers, out);
}